// round 10
// baseline (speedup 1.0000x reference)
#include <cuda_runtime.h>
#include <cuda_fp16.h>

#define OUT_HW 7
#define NBINS 49
#define NSAMP 196          // 49 bins * 4 samples
#define SPATIAL_SCALE 0.25f
#define CC 256
#define HH 200
#define WW 272
#define BB 4
#define HWSZ (HH * WW)

// Scratch: NHWC fp16 copy of features (~111 MB).
__device__ __half g_nhwc[(size_t)BB * HWSZ * CC];

// NCHW [C,H,W] of batch b (fp32) -> NHWC fp16 slice. One batch per launch.
__global__ __launch_bounds__(256) void nchw_to_nhwc(const float* __restrict__ in,
                                                    int b) {
    __shared__ float tile[32][129];
    const int hw0 = blockIdx.x * 128;
    const int c0  = blockIdx.y * 32;
    const int tx = threadIdx.x, ty = threadIdx.y;
    const int tid = ty * 32 + tx;
    const float* src = in + (size_t)b * CC * HWSZ + (size_t)c0 * HWSZ + hw0;
    __half* dst = g_nhwc + (size_t)b * HWSZ * CC + c0;

#pragma unroll
    for (int k = 0; k < 4; k++) {
        const int c = ty + k * 8;
        const float* s = src + (size_t)c * HWSZ;
#pragma unroll
        for (int m = 0; m < 4; m++) {
            tile[c][tx + m * 32] = s[tx + m * 32];
        }
    }
    __syncthreads();

#pragma unroll
    for (int i = 0; i < 2; i++) {
        const int s    = tid + i * 256;
        const int hw   = s >> 2;
        const int cgrp = s & 3;
        const int cb   = cgrp * 8;
        float v0 = tile[cb + 0][hw], v1 = tile[cb + 1][hw];
        float v2 = tile[cb + 2][hw], v3 = tile[cb + 3][hw];
        float v4 = tile[cb + 4][hw], v5 = tile[cb + 5][hw];
        float v6 = tile[cb + 6][hw], v7 = tile[cb + 7][hw];
        __half2 h0 = __floats2half2_rn(v0, v1);
        __half2 h1 = __floats2half2_rn(v2, v3);
        __half2 h2 = __floats2half2_rn(v4, v5);
        __half2 h3 = __floats2half2_rn(v6, v7);
        uint4 r;
        r.x = *(unsigned*)&h0; r.y = *(unsigned*)&h1;
        r.z = *(unsigned*)&h2; r.w = *(unsigned*)&h3;
        *(uint4*)(dst + (size_t)(hw0 + hw) * CC + cb) = r;
    }
}

__device__ __forceinline__ void acc4(const uint2 u, float w,
                                     float& a0, float& a1, float& a2, float& a3) {
    const float2 fa = __half22float2(*(const __half2*)&u.x);
    const float2 fb = __half22float2(*(const __half2*)&u.y);
    a0 = fmaf(w, fa.x, a0); a1 = fmaf(w, fa.y, a1);
    a2 = fmaf(w, fb.x, a2); a3 = fmaf(w, fb.y, a3);
}

// One block per (roi, channel-half); processes only rois of `batch`,
// others early-exit. Internals identical to the R9 kernel.
__global__ __launch_bounds__(256) void roi_align_kernel(
    const float* __restrict__ rois, float* __restrict__ out, int batch) {
    const int n  = blockIdx.x;
    const int cg = blockIdx.y;

    const int b0 = (int)rois[n * 5 + 0];
    if (b0 != batch) return;

    __shared__ __align__(16) float sbuf[128 * NBINS];   // 25,088 B
    __shared__ __align__(16) float4 s_w[NSAMP];         // 3,136 B
    __shared__ int s_off[NSAMP];                        //   784 B

    const int tx = threadIdx.x, ty = threadIdx.y;
    const int tid = ty * 32 + tx;

    if (tid < NSAMP) {
        const int bin = tid >> 2;
        const int smp = tid & 3;
        const int ph = bin / 7, pw = bin - ph * 7;
        const int jy = ph * 2 + (smp >> 1);
        const int jx = pw * 2 + (smp & 1);

        const float x1r = rois[n * 5 + 1] * SPATIAL_SCALE;
        const float y1r = rois[n * 5 + 2] * SPATIAL_SCALE;
        const float x2r = rois[n * 5 + 3] * SPATIAL_SCALE;
        const float y2r = rois[n * 5 + 4] * SPATIAL_SCALE;
        const float bw = fmaxf(x2r - x1r, 1.0f) * (1.0f / 7.0f);
        const float bh = fmaxf(y2r - y1r, 1.0f) * (1.0f / 7.0f);

        const float yc = y1r + ((float)jy + 0.5f) * 0.5f * bh;
        const float xc = x1r + ((float)jx + 0.5f) * 0.5f * bw;
        const bool valid = (yc > -1.0f) && (yc < (float)HH) &&
                           (xc > -1.0f) && (xc < (float)WW);

        float y = fminf(fmaxf(yc, 0.0f), (float)(HH - 1));
        float x = fminf(fmaxf(xc, 0.0f), (float)(WW - 1));
        float y0f = fminf(floorf(y), (float)(HH - 2));
        float x0f = fminf(floorf(x), (float)(WW - 2));
        const float ly = y - y0f, lx = x - x0f;
        const float hy = 1.0f - ly, hx = 1.0f - lx;

        const float vm = valid ? 0.25f : 0.0f;   // fold mean + validity
        s_w[tid] = make_float4(hy * hx * vm, hy * lx * vm,
                               ly * hx * vm, ly * lx * vm);
        s_off[tid] = ((int)y0f * WW + (int)x0f) * CC;
    }
    __syncthreads();

    const __half* fbase = g_nhwc + (size_t)b0 * HWSZ * CC + cg * 128 + tx * 4;

#pragma unroll 2
    for (int bin = ty; bin < NBINS; bin += 8) {
        float a0 = 0.f, a1 = 0.f, a2 = 0.f, a3 = 0.f;
#pragma unroll
        for (int sp = 0; sp < 2; sp++) {
            const int iA = bin * 4 + sp * 2;
            const int iB = iA + 1;
            const __half* pA = fbase + s_off[iA];
            const __half* pB = fbase + s_off[iB];
            const float4 wA = s_w[iA];
            const float4 wB = s_w[iB];
            const uint2 uA0 = *(const uint2*)(pA);
            const uint2 uA1 = *(const uint2*)(pA + CC);
            const uint2 uA2 = *(const uint2*)(pA + (size_t)WW * CC);
            const uint2 uA3 = *(const uint2*)(pA + (size_t)WW * CC + CC);
            const uint2 uB0 = *(const uint2*)(pB);
            const uint2 uB1 = *(const uint2*)(pB + CC);
            const uint2 uB2 = *(const uint2*)(pB + (size_t)WW * CC);
            const uint2 uB3 = *(const uint2*)(pB + (size_t)WW * CC + CC);
            acc4(uA0, wA.x, a0, a1, a2, a3);
            acc4(uA1, wA.y, a0, a1, a2, a3);
            acc4(uA2, wA.z, a0, a1, a2, a3);
            acc4(uA3, wA.w, a0, a1, a2, a3);
            acc4(uB0, wB.x, a0, a1, a2, a3);
            acc4(uB1, wB.y, a0, a1, a2, a3);
            acc4(uB2, wB.z, a0, a1, a2, a3);
            acc4(uB3, wB.w, a0, a1, a2, a3);
        }
        const int cl = tx * 4;
        sbuf[(cl + 0) * NBINS + bin] = a0;
        sbuf[(cl + 1) * NBINS + bin] = a1;
        sbuf[(cl + 2) * NBINS + bin] = a2;
        sbuf[(cl + 3) * NBINS + bin] = a3;
    }
    __syncthreads();

    float4* o = (float4*)(out + (size_t)n * (CC * NBINS) + (size_t)cg * 128 * NBINS);
    const float4* s4 = (const float4*)sbuf;
#pragma unroll
    for (int i = tid; i < 128 * NBINS / 4; i += 256) o[i] = s4[i];
}

// Host-side stream/event plumbing, created once at static init (host objects
// only — no device memory). Graph capture turns the event record/wait pairs
// into graph edges, overlapping roi pass b with transpose of batches b+1..3.
static cudaStream_t g_side;
static cudaEvent_t  g_fork[BB];
static cudaEvent_t  g_join;
namespace {
struct CudaInit {
    CudaInit() {
        cudaStreamCreate(&g_side);
        for (int i = 0; i < BB; i++)
            cudaEventCreateWithFlags(&g_fork[i], cudaEventDisableTiming);
        cudaEventCreateWithFlags(&g_join, cudaEventDisableTiming);
    }
};
static CudaInit g_cuda_init;
}

extern "C" void kernel_launch(void* const* d_in, const int* in_sizes, int n_in,
                              void* d_out, int out_size) {
    const float* features = (const float*)d_in[0];
    const float* rois     = (const float*)d_in[1];
    float* out            = (float*)d_out;
    const int nrois = in_sizes[1] / 5;

    const dim3 tgrid(HWSZ / 128, CC / 32);   // per-batch transpose
    for (int b = 0; b < BB; b++) {
        nchw_to_nhwc<<<tgrid, dim3(32, 8)>>>(features, b);
        cudaEventRecord(g_fork[b], 0);
        cudaStreamWaitEvent(g_side, g_fork[b], 0);
        roi_align_kernel<<<dim3(nrois, 2), dim3(32, 8), 0, g_side>>>(rois, out, b);
    }
    cudaEventRecord(g_join, g_side);
    cudaStreamWaitEvent(0, g_join, 0);
}

// round 12
// speedup vs baseline: 1.2496x; 1.2496x over previous
#include <cuda_runtime.h>
#include <cuda_fp16.h>

#define OUT_HW 7
#define NBINS 49
#define NSAMP 196          // 49 bins * 4 samples
#define SPATIAL_SCALE 0.25f
#define CC 256
#define HH 200
#define WW 272
#define BB 4
#define HWSZ (HH * WW)
#define NBH 25             // max bins per block (bin-split)

// Scratch: NHWC fp16 copy of features (~111 MB).
__device__ __half g_nhwc[(size_t)BB * HWSZ * CC];

// NCHW [B,C,H,W] fp32 -> NHWC [B,H,W,C] fp16. At DRAM roofline.
__global__ __launch_bounds__(256) void nchw_to_nhwc(const float* __restrict__ in) {
    __shared__ float tile[32][129];
    const int b   = blockIdx.z;
    const int hw0 = blockIdx.x * 128;
    const int c0  = blockIdx.y * 32;
    const int tx = threadIdx.x, ty = threadIdx.y;
    const int tid = ty * 32 + tx;
    const float* src = in + (size_t)b * CC * HWSZ + (size_t)c0 * HWSZ + hw0;
    __half* dst = g_nhwc + (size_t)b * HWSZ * CC + c0;

#pragma unroll
    for (int k = 0; k < 4; k++) {
        const int c = ty + k * 8;
        const float* s = src + (size_t)c * HWSZ;
#pragma unroll
        for (int m = 0; m < 4; m++) {
            tile[c][tx + m * 32] = s[tx + m * 32];
        }
    }
    __syncthreads();

#pragma unroll
    for (int i = 0; i < 2; i++) {
        const int s    = tid + i * 256;
        const int hw   = s >> 2;
        const int cgrp = s & 3;
        const int cb   = cgrp * 8;
        float v0 = tile[cb + 0][hw], v1 = tile[cb + 1][hw];
        float v2 = tile[cb + 2][hw], v3 = tile[cb + 3][hw];
        float v4 = tile[cb + 4][hw], v5 = tile[cb + 5][hw];
        float v6 = tile[cb + 6][hw], v7 = tile[cb + 7][hw];
        __half2 h0 = __floats2half2_rn(v0, v1);
        __half2 h1 = __floats2half2_rn(v2, v3);
        __half2 h2 = __floats2half2_rn(v4, v5);
        __half2 h3 = __floats2half2_rn(v6, v7);
        uint4 r;
        r.x = *(unsigned*)&h0; r.y = *(unsigned*)&h1;
        r.z = *(unsigned*)&h2; r.w = *(unsigned*)&h3;
        *(uint4*)(dst + (size_t)(hw0 + hw) * CC + cb) = r;
    }
}

__device__ __forceinline__ void acc4(const uint2 u, float w,
                                     float& a0, float& a1, float& a2, float& a3) {
    const float2 fa = __half22float2(*(const __half2*)&u.x);
    const float2 fb = __half22float2(*(const __half2*)&u.y);
    a0 = fmaf(w, fa.x, a0); a1 = fmaf(w, fa.y, a1);
    a2 = fmaf(w, fb.x, a2); a3 = fmaf(w, fb.y, a3);
}

// One block per (roi, channel-half, bin-half). blockDim=(32,8).
// Branch-free mainloop; per-sample {offset,weights} table in smem.
__global__ __launch_bounds__(256) void roi_align_kernel(
    const float* __restrict__ rois, float* __restrict__ out) {
    const int n  = blockIdx.x;
    const int cg = blockIdx.y;
    const int bh = blockIdx.z;
    const int bin0 = bh * NBH;               // 0 or 25
    const int nb   = bh ? (NBINS - NBH) : NBH;  // 24 or 25

    __shared__ __align__(16) float sbuf[128 * NBH];     // 12,800 B
    __shared__ __align__(16) float4 s_w[NSAMP];         //  3,136 B
    __shared__ int s_off[NSAMP];                        //    784 B
    __shared__ int s_b;

    const int tx = threadIdx.x, ty = threadIdx.y;
    const int tid = ty * 32 + tx;

    if (tid < NSAMP) {
        const int bin = tid >> 2;
        const int smp = tid & 3;
        const int ph = bin / 7, pw = bin - ph * 7;
        const int jy = ph * 2 + (smp >> 1);
        const int jx = pw * 2 + (smp & 1);

        const float x1r = rois[n * 5 + 1] * SPATIAL_SCALE;
        const float y1r = rois[n * 5 + 2] * SPATIAL_SCALE;
        const float x2r = rois[n * 5 + 3] * SPATIAL_SCALE;
        const float y2r = rois[n * 5 + 4] * SPATIAL_SCALE;
        const float bw = fmaxf(x2r - x1r, 1.0f) * (1.0f / 7.0f);
        const float bh_ = fmaxf(y2r - y1r, 1.0f) * (1.0f / 7.0f);

        const float yc = y1r + ((float)jy + 0.5f) * 0.5f * bh_;
        const float xc = x1r + ((float)jx + 0.5f) * 0.5f * bw;
        const bool valid = (yc > -1.0f) && (yc < (float)HH) &&
                           (xc > -1.0f) && (xc < (float)WW);

        float y = fminf(fmaxf(yc, 0.0f), (float)(HH - 1));
        float x = fminf(fmaxf(xc, 0.0f), (float)(WW - 1));
        float y0f = fminf(floorf(y), (float)(HH - 2));
        float x0f = fminf(floorf(x), (float)(WW - 2));
        const float ly = y - y0f, lx = x - x0f;
        const float hy = 1.0f - ly, hx = 1.0f - lx;

        const float vm = valid ? 0.25f : 0.0f;   // fold mean + validity
        s_w[tid] = make_float4(hy * hx * vm, hy * lx * vm,
                               ly * hx * vm, ly * lx * vm);
        s_off[tid] = ((int)y0f * WW + (int)x0f) * CC;
    }
    if (tid == 0) s_b = (int)rois[n * 5 + 0];
    __syncthreads();

    const __half* fbase = g_nhwc + (size_t)s_b * HWSZ * CC + cg * 128 + tx * 4;

#pragma unroll 2
    for (int bi = ty; bi < nb; bi += 8) {
        const int bin = bin0 + bi;
        float a0 = 0.f, a1 = 0.f, a2 = 0.f, a3 = 0.f;
#pragma unroll
        for (int sp = 0; sp < 2; sp++) {
            const int iA = bin * 4 + sp * 2;
            const int iB = iA + 1;
            const __half* pA = fbase + s_off[iA];
            const __half* pB = fbase + s_off[iB];
            const float4 wA = s_w[iA];
            const float4 wB = s_w[iB];
            const uint2 uA0 = *(const uint2*)(pA);
            const uint2 uA1 = *(const uint2*)(pA + CC);
            const uint2 uA2 = *(const uint2*)(pA + (size_t)WW * CC);
            const uint2 uA3 = *(const uint2*)(pA + (size_t)WW * CC + CC);
            const uint2 uB0 = *(const uint2*)(pB);
            const uint2 uB1 = *(const uint2*)(pB + CC);
            const uint2 uB2 = *(const uint2*)(pB + (size_t)WW * CC);
            const uint2 uB3 = *(const uint2*)(pB + (size_t)WW * CC + CC);
            acc4(uA0, wA.x, a0, a1, a2, a3);
            acc4(uA1, wA.y, a0, a1, a2, a3);
            acc4(uA2, wA.z, a0, a1, a2, a3);
            acc4(uA3, wA.w, a0, a1, a2, a3);
            acc4(uB0, wB.x, a0, a1, a2, a3);
            acc4(uB1, wB.y, a0, a1, a2, a3);
            acc4(uB2, wB.z, a0, a1, a2, a3);
            acc4(uB3, wB.w, a0, a1, a2, a3);
        }
        const int cl = tx * 4;
        sbuf[(cl + 0) * NBH + bi] = a0;
        sbuf[(cl + 1) * NBH + bi] = a1;
        sbuf[(cl + 2) * NBH + bi] = a2;
        sbuf[(cl + 3) * NBH + bi] = a3;
    }
    __syncthreads();

    // Copy-out: per channel, nb consecutive floats at out[c*49 + bin0].
    float* o = out + (size_t)n * (CC * NBINS) + (size_t)cg * 128 * NBINS + bin0;
    const int total = 128 * nb;
    for (int i = tid; i < total; i += 256) {
        const int c = i / nb;
        const int j = i - c * nb;
        o[c * NBINS + j] = sbuf[c * NBH + j];
    }
}

extern "C" void kernel_launch(void* const* d_in, const int* in_sizes, int n_in,
                              void* d_out, int out_size) {
    const float* features = (const float*)d_in[0];
    const float* rois     = (const float*)d_in[1];
    float* out            = (float*)d_out;
    const int nrois = in_sizes[1] / 5;

    dim3 tgrid(HWSZ / 128, CC / 32, BB);   // 425 x 8 x 4
    nchw_to_nhwc<<<tgrid, dim3(32, 8)>>>(features);
    roi_align_kernel<<<dim3(nrois, 2, 2), dim3(32, 8)>>>(rois, out);
}